// round 1
// baseline (speedup 1.0000x reference)
#include <cuda_runtime.h>

// Problem constants
#define Bq   4
#define Sq   4
#define Lq_  1024
#define Dq   1024
#define Hq   16
#define DEP  64
#define BSq  16          // B*S
#define BSHq 256         // B*S*H
#define MROWS 16384      // B*S*L
#define OUT_ELEMS 16777216   // B*S*L*D  (== B*S*L*L here)

// Scratch (static __device__ — allocation-free rule)
__device__ float g_qh[16777216];     // [bsh][l][d]
__device__ float g_kh[16777216];
__device__ float g_vh[16777216];
__device__ float g_ctx[16777216];    // merged [bs*L + l][D]
__device__ float g_probs[268435456]; // [bsh][q][k]  (logits then probs in place)

// ---------------------------------------------------------------------------
// SGEMM: C[M,N] = A[M,K] @ W[K,N] + bias.  128x128x8 tiles, 256 thr, 8x8/thr.
// head_split=1 writes C into head-split layout [bs][h][l][d].
// ---------------------------------------------------------------------------
__global__ __launch_bounds__(256) void sgemm_bias(
    const float* __restrict__ A, const float* __restrict__ W,
    const float* __restrict__ bias, float* __restrict__ C,
    int K, int N, int head_split)
{
    __shared__ float As[8][128];
    __shared__ float Bs[8][128];

    const int tid = threadIdx.x;
    const int tx = tid & 15;
    const int ty = tid >> 4;
    const int rowBase = blockIdx.y * 128;
    const int colBase = blockIdx.x * 128;

    const int aRow = tid >> 1;
    const int aK   = (tid & 1) * 4;
    const int bRow = tid >> 5;
    const int bC   = (tid & 31) * 4;

    float acc[8][8];
#pragma unroll
    for (int i = 0; i < 8; i++)
#pragma unroll
        for (int j = 0; j < 8; j++) acc[i][j] = 0.f;

    for (int k0 = 0; k0 < K; k0 += 8) {
        float4 av = *(const float4*)(A + (long long)(rowBase + aRow) * K + k0 + aK);
        As[aK + 0][aRow] = av.x;
        As[aK + 1][aRow] = av.y;
        As[aK + 2][aRow] = av.z;
        As[aK + 3][aRow] = av.w;
        *(float4*)&Bs[bRow][bC] =
            *(const float4*)(W + (long long)(k0 + bRow) * N + colBase + bC);
        __syncthreads();

#pragma unroll
        for (int k = 0; k < 8; k++) {
            float a[8], b[8];
            *(float4*)&a[0] = *(const float4*)&As[k][ty * 4];
            *(float4*)&a[4] = *(const float4*)&As[k][ty * 4 + 64];
            *(float4*)&b[0] = *(const float4*)&Bs[k][tx * 4];
            *(float4*)&b[4] = *(const float4*)&Bs[k][tx * 4 + 64];
#pragma unroll
            for (int i = 0; i < 8; i++)
#pragma unroll
                for (int j = 0; j < 8; j++)
                    acc[i][j] += a[i] * b[j];
        }
        __syncthreads();
    }

#pragma unroll
    for (int ih = 0; ih < 2; ih++)
#pragma unroll
        for (int i = 0; i < 4; i++) {
            int row = rowBase + ih * 64 + ty * 4 + i;
            int bs = row >> 10;       // row / 1024
            int l  = row & 1023;
#pragma unroll
            for (int jh = 0; jh < 2; jh++)
#pragma unroll
                for (int j = 0; j < 4; j++) {
                    int col = colBase + jh * 64 + tx * 4 + j;
                    float val = acc[ih * 4 + i][jh * 4 + j] + bias[col];
                    if (head_split) {
                        int h = col >> 6;
                        int d = col & 63;
                        // ((bs*16 + h)*1024 + l)*64 + d
                        C[(((bs << 4) + h) << 16) + (l << 6) + d] = val;
                    } else {
                        C[(long long)row * N + col] = val;
                    }
                }
        }
}

// ---------------------------------------------------------------------------
// QK^T logits: per (bsh, q-tile 64, k-tile 64) -> g_probs = logits/8 + mask*NEG
// ---------------------------------------------------------------------------
__global__ __launch_bounds__(256) void qk_logits_kernel(const float* __restrict__ mask)
{
    __shared__ float Qs[64][65];  // [q][d], pad 65 -> broadcast-friendly scalar loads
    __shared__ float Ks[64][65];  // [kcol][d]

    const int tid = threadIdx.x;
    const int tx = tid & 15;
    const int ty = tid >> 4;
    const int k0  = blockIdx.x * 64;
    const int q0  = blockIdx.y * 64;
    const int bsh = blockIdx.z;
    const int bs  = bsh >> 4;

    const float* Qg = g_qh + (long long)bsh * 65536;
    const float* Kg = g_kh + (long long)bsh * 65536;

#pragma unroll
    for (int it = 0; it < 4; it++) {
        int f4 = tid + it * 256;          // 0..1023
        int r  = f4 >> 4;
        int c4 = (f4 & 15) * 4;
        float4 qv = *(const float4*)(Qg + (q0 + r) * 64 + c4);
        Qs[r][c4 + 0] = qv.x; Qs[r][c4 + 1] = qv.y;
        Qs[r][c4 + 2] = qv.z; Qs[r][c4 + 3] = qv.w;
        float4 kv = *(const float4*)(Kg + (k0 + r) * 64 + c4);
        Ks[r][c4 + 0] = kv.x; Ks[r][c4 + 1] = kv.y;
        Ks[r][c4 + 2] = kv.z; Ks[r][c4 + 3] = kv.w;
    }
    __syncthreads();

    float acc[4][4];
#pragma unroll
    for (int i = 0; i < 4; i++)
#pragma unroll
        for (int j = 0; j < 4; j++) acc[i][j] = 0.f;

#pragma unroll 16
    for (int k = 0; k < 64; k++) {
        float a0 = Qs[ty * 4 + 0][k];
        float a1 = Qs[ty * 4 + 1][k];
        float a2 = Qs[ty * 4 + 2][k];
        float a3 = Qs[ty * 4 + 3][k];
        float b0 = Ks[tx * 4 + 0][k];
        float b1 = Ks[tx * 4 + 1][k];
        float b2 = Ks[tx * 4 + 2][k];
        float b3 = Ks[tx * 4 + 3][k];
        acc[0][0] += a0 * b0; acc[0][1] += a0 * b1; acc[0][2] += a0 * b2; acc[0][3] += a0 * b3;
        acc[1][0] += a1 * b0; acc[1][1] += a1 * b1; acc[1][2] += a1 * b2; acc[1][3] += a1 * b3;
        acc[2][0] += a2 * b0; acc[2][1] += a2 * b1; acc[2][2] += a2 * b2; acc[2][3] += a2 * b3;
        acc[3][0] += a3 * b0; acc[3][1] += a3 * b1; acc[3][2] += a3 * b2; acc[3][3] += a3 * b3;
    }

    float* Pg = g_probs + ((long long)bsh << 20);
    const float* Mg = mask + ((long long)bs << 20);
#pragma unroll
    for (int i = 0; i < 4; i++) {
        int q = q0 + ty * 4 + i;
#pragma unroll
        for (int j = 0; j < 4; j++) {
            int kc = k0 + tx * 4 + j;
            Pg[q * 1024 + kc] = acc[i][j] * 0.125f + Mg[q * 1024 + kc] * (-1.0e9f);
        }
    }
}

// ---------------------------------------------------------------------------
// Row softmax in-place over g_probs (1024 per row, 262144 rows)
// ---------------------------------------------------------------------------
__global__ __launch_bounds__(256) void softmax_kernel()
{
    __shared__ float red_max[8];
    __shared__ float red_sum[8];

    const long long row = blockIdx.x;
    float* p = g_probs + row * 1024;
    const int tid  = threadIdx.x;
    const int lane = tid & 31;
    const int warp = tid >> 5;

    float4 v = ((float4*)p)[tid];
    float m = fmaxf(fmaxf(v.x, v.y), fmaxf(v.z, v.w));
#pragma unroll
    for (int o = 16; o > 0; o >>= 1)
        m = fmaxf(m, __shfl_xor_sync(0xffffffffu, m, o));
    if (lane == 0) red_max[warp] = m;
    __syncthreads();

    float rowmax = red_max[0];
#pragma unroll
    for (int i = 1; i < 8; i++) rowmax = fmaxf(rowmax, red_max[i]);

    float e0 = __expf(v.x - rowmax);
    float e1 = __expf(v.y - rowmax);
    float e2 = __expf(v.z - rowmax);
    float e3 = __expf(v.w - rowmax);
    float s = e0 + e1 + e2 + e3;
#pragma unroll
    for (int o = 16; o > 0; o >>= 1)
        s += __shfl_xor_sync(0xffffffffu, s, o);
    if (lane == 0) red_sum[warp] = s;
    __syncthreads();

    float tot = 0.f;
#pragma unroll
    for (int i = 0; i < 8; i++) tot += red_sum[i];
    float inv = __frcp_rn(tot);

    float4 o4;
    o4.x = e0 * inv; o4.y = e1 * inv; o4.z = e2 * inv; o4.w = e3 * inv;
    ((float4*)p)[tid] = o4;
}

// ---------------------------------------------------------------------------
// ctx = probs @ V per (bsh), written merged [bs*L + q][h*64 + d]
// 64x64 tile, BK=16, 256 thr, 4x4/thr
// ---------------------------------------------------------------------------
__global__ __launch_bounds__(256) void ctx_kernel()
{
    __shared__ float Ps[64][17];
    __shared__ float Vs[16][64];

    const int m0  = blockIdx.x * 64;
    const int bsh = blockIdx.y;
    const int h   = bsh & 15;
    const int bs  = bsh >> 4;

    const float* P = g_probs + ((long long)bsh << 20);
    const float* V = g_vh + (long long)bsh * 65536;

    const int tid = threadIdx.x;
    const int tx = tid & 15;
    const int ty = tid >> 4;
    const int pr  = tid >> 2;
    const int pc4 = (tid & 3) * 4;
    const int vr  = tid >> 4;
    const int vc4 = (tid & 15) * 4;

    float acc[4][4];
#pragma unroll
    for (int i = 0; i < 4; i++)
#pragma unroll
        for (int j = 0; j < 4; j++) acc[i][j] = 0.f;

    for (int k0 = 0; k0 < 1024; k0 += 16) {
        float4 pa = *(const float4*)(P + (m0 + pr) * 1024 + k0 + pc4);
        Ps[pr][pc4 + 0] = pa.x; Ps[pr][pc4 + 1] = pa.y;
        Ps[pr][pc4 + 2] = pa.z; Ps[pr][pc4 + 3] = pa.w;
        *(float4*)&Vs[vr][vc4] = *(const float4*)(V + (k0 + vr) * 64 + vc4);
        __syncthreads();

#pragma unroll
        for (int k = 0; k < 16; k++) {
            float a0 = Ps[ty * 4 + 0][k];
            float a1 = Ps[ty * 4 + 1][k];
            float a2 = Ps[ty * 4 + 2][k];
            float a3 = Ps[ty * 4 + 3][k];
            float b0 = Vs[k][tx * 4 + 0];
            float b1 = Vs[k][tx * 4 + 1];
            float b2 = Vs[k][tx * 4 + 2];
            float b3 = Vs[k][tx * 4 + 3];
            acc[0][0] += a0 * b0; acc[0][1] += a0 * b1; acc[0][2] += a0 * b2; acc[0][3] += a0 * b3;
            acc[1][0] += a1 * b0; acc[1][1] += a1 * b1; acc[1][2] += a1 * b2; acc[1][3] += a1 * b3;
            acc[2][0] += a2 * b0; acc[2][1] += a2 * b1; acc[2][2] += a2 * b2; acc[2][3] += a2 * b3;
            acc[3][0] += a3 * b0; acc[3][1] += a3 * b1; acc[3][2] += a3 * b2; acc[3][3] += a3 * b3;
        }
        __syncthreads();
    }

#pragma unroll
    for (int i = 0; i < 4; i++) {
        int q = m0 + ty * 4 + i;
        float* dst = g_ctx + ((long long)(bs * 1024 + q)) * 1024 + h * 64;
#pragma unroll
        for (int j = 0; j < 4; j++)
            dst[tx * 4 + j] = acc[i][j];
    }
}

// ---------------------------------------------------------------------------
// attn_mean = mean over heads of probs
// ---------------------------------------------------------------------------
__global__ __launch_bounds__(256) void head_mean_kernel(float* __restrict__ outm)
{
    const int i = blockIdx.x * 256 + threadIdx.x;  // < 16777216
    const int bs  = i >> 20;
    const int rem = i & 0xFFFFF;
    const float* base = g_probs + ((long long)bs << 24) + rem;
    float s = 0.f;
#pragma unroll
    for (int h = 0; h < 16; h++)
        s += base[(long long)h << 20];
    outm[i] = s * 0.0625f;
}

// ---------------------------------------------------------------------------
extern "C" void kernel_launch(void* const* d_in, const int* in_sizes, int n_in,
                              void* d_out, int out_size)
{
    const float* q    = (const float*)d_in[0];
    const float* k    = (const float*)d_in[1];
    const float* v    = (const float*)d_in[2];
    const float* mask = (const float*)d_in[3];
    const float* wq   = (const float*)d_in[4];
    const float* bq   = (const float*)d_in[5];
    const float* wk   = (const float*)d_in[6];
    const float* bk   = (const float*)d_in[7];
    const float* wv   = (const float*)d_in[8];
    const float* bv   = (const float*)d_in[9];
    const float* wo   = (const float*)d_in[10];
    const float* bo   = (const float*)d_in[11];

    float* out       = (float*)d_out;
    float* attn_mean = out + OUT_ELEMS;

    float *p_qh, *p_kh, *p_vh, *p_ctx;
    cudaGetSymbolAddress((void**)&p_qh,  g_qh);
    cudaGetSymbolAddress((void**)&p_kh,  g_kh);
    cudaGetSymbolAddress((void**)&p_vh,  g_vh);
    cudaGetSymbolAddress((void**)&p_ctx, g_ctx);

    dim3 gemmGrid(Dq / 128, MROWS / 128);   // (8, 128)

    // QKV projections (head-split outputs)
    sgemm_bias<<<gemmGrid, 256>>>(q, wq, bq, p_qh, Dq, Dq, 1);
    sgemm_bias<<<gemmGrid, 256>>>(k, wk, bk, p_kh, Dq, Dq, 1);
    sgemm_bias<<<gemmGrid, 256>>>(v, wv, bv, p_vh, Dq, Dq, 1);

    // logits (+scale+mask) -> g_probs
    qk_logits_kernel<<<dim3(16, 16, BSHq), 256>>>(mask);

    // softmax in place
    softmax_kernel<<<BSHq * Lq_, 256>>>();

    // ctx = probs @ V, merged layout
    ctx_kernel<<<dim3(16, BSHq), 256>>>();

    // attn_mean output
    head_mean_kernel<<<OUT_ELEMS / 256, 256>>>(attn_mean);

    // output projection
    sgemm_bias<<<gemmGrid, 256>>>(p_ctx, wo, bo, out, Dq, Dq, 0);
}

// round 2
// speedup vs baseline: 1.0004x; 1.0004x over previous
#include <cuda_runtime.h>

// Problem constants
#define Bq   4
#define Sq   4
#define Lq_  1024
#define Dq   1024
#define Hq   16
#define DEP  64
#define BSq  16          // B*S
#define BSHq 256         // B*S*H
#define MROWS 16384      // B*S*L
#define OUT_ELEMS 16777216   // B*S*L*D  (== B*S*L*L here)

// Scratch (static __device__ — allocation-free rule)
__device__ float g_qh[16777216];     // [bsh][l][d]
__device__ float g_kh[16777216];
__device__ float g_vh[16777216];
__device__ float g_ctx[16777216];    // merged [bs*L + l][D]
__device__ float g_probs[268435456]; // [bsh][q][k]  (logits then probs in place)

// ---------------------------------------------------------------------------
// SGEMM: C[M,N] = A[M,K] @ W[K,N] + bias.  128x128x8 tiles, 256 thr, 8x8/thr.
// head_split=1 writes C into head-split layout [bs][h][l][d].
// ---------------------------------------------------------------------------
__global__ __launch_bounds__(256) void sgemm_bias(
    const float* __restrict__ A, const float* __restrict__ W,
    const float* __restrict__ bias, float* __restrict__ C,
    int K, int N, int head_split)
{
    __shared__ float As[8][128];
    __shared__ float Bs[8][128];

    const int tid = threadIdx.x;
    const int tx = tid & 15;
    const int ty = tid >> 4;
    const int rowBase = blockIdx.y * 128;
    const int colBase = blockIdx.x * 128;

    const int aRow = tid >> 1;
    const int aK   = (tid & 1) * 4;
    const int bRow = tid >> 5;
    const int bC   = (tid & 31) * 4;

    float acc[8][8];
#pragma unroll
    for (int i = 0; i < 8; i++)
#pragma unroll
        for (int j = 0; j < 8; j++) acc[i][j] = 0.f;

    for (int k0 = 0; k0 < K; k0 += 8) {
        float4 av = *(const float4*)(A + (long long)(rowBase + aRow) * K + k0 + aK);
        As[aK + 0][aRow] = av.x;
        As[aK + 1][aRow] = av.y;
        As[aK + 2][aRow] = av.z;
        As[aK + 3][aRow] = av.w;
        *(float4*)&Bs[bRow][bC] =
            *(const float4*)(W + (long long)(k0 + bRow) * N + colBase + bC);
        __syncthreads();

#pragma unroll
        for (int k = 0; k < 8; k++) {
            float a[8], b[8];
            *(float4*)&a[0] = *(const float4*)&As[k][ty * 4];
            *(float4*)&a[4] = *(const float4*)&As[k][ty * 4 + 64];
            *(float4*)&b[0] = *(const float4*)&Bs[k][tx * 4];
            *(float4*)&b[4] = *(const float4*)&Bs[k][tx * 4 + 64];
#pragma unroll
            for (int i = 0; i < 8; i++)
#pragma unroll
                for (int j = 0; j < 8; j++)
                    acc[i][j] += a[i] * b[j];
        }
        __syncthreads();
    }

#pragma unroll
    for (int ih = 0; ih < 2; ih++)
#pragma unroll
        for (int i = 0; i < 4; i++) {
            int row = rowBase + ih * 64 + ty * 4 + i;
            int bs = row >> 10;       // row / 1024
            int l  = row & 1023;
#pragma unroll
            for (int jh = 0; jh < 2; jh++)
#pragma unroll
                for (int j = 0; j < 4; j++) {
                    int col = colBase + jh * 64 + tx * 4 + j;
                    float val = acc[ih * 4 + i][jh * 4 + j] + bias[col];
                    if (head_split) {
                        int h = col >> 6;
                        int d = col & 63;
                        // ((bs*16 + h)*1024 + l)*64 + d
                        C[(((bs << 4) + h) << 16) + (l << 6) + d] = val;
                    } else {
                        C[(long long)row * N + col] = val;
                    }
                }
        }
}

// ---------------------------------------------------------------------------
// QK^T logits: per (bsh, q-tile 64, k-tile 64) -> g_probs = logits/8 + mask*NEG
// ---------------------------------------------------------------------------
__global__ __launch_bounds__(256) void qk_logits_kernel(const float* __restrict__ mask)
{
    __shared__ float Qs[64][65];  // [q][d], pad 65 -> broadcast-friendly scalar loads
    __shared__ float Ks[64][65];  // [kcol][d]

    const int tid = threadIdx.x;
    const int tx = tid & 15;
    const int ty = tid >> 4;
    const int k0  = blockIdx.x * 64;
    const int q0  = blockIdx.y * 64;
    const int bsh = blockIdx.z;
    const int bs  = bsh >> 4;

    const float* Qg = g_qh + (long long)bsh * 65536;
    const float* Kg = g_kh + (long long)bsh * 65536;

#pragma unroll
    for (int it = 0; it < 4; it++) {
        int f4 = tid + it * 256;          // 0..1023
        int r  = f4 >> 4;
        int c4 = (f4 & 15) * 4;
        float4 qv = *(const float4*)(Qg + (q0 + r) * 64 + c4);
        Qs[r][c4 + 0] = qv.x; Qs[r][c4 + 1] = qv.y;
        Qs[r][c4 + 2] = qv.z; Qs[r][c4 + 3] = qv.w;
        float4 kv = *(const float4*)(Kg + (k0 + r) * 64 + c4);
        Ks[r][c4 + 0] = kv.x; Ks[r][c4 + 1] = kv.y;
        Ks[r][c4 + 2] = kv.z; Ks[r][c4 + 3] = kv.w;
    }
    __syncthreads();

    float acc[4][4];
#pragma unroll
    for (int i = 0; i < 4; i++)
#pragma unroll
        for (int j = 0; j < 4; j++) acc[i][j] = 0.f;

#pragma unroll 16
    for (int k = 0; k < 64; k++) {
        float a0 = Qs[ty * 4 + 0][k];
        float a1 = Qs[ty * 4 + 1][k];
        float a2 = Qs[ty * 4 + 2][k];
        float a3 = Qs[ty * 4 + 3][k];
        float b0 = Ks[tx * 4 + 0][k];
        float b1 = Ks[tx * 4 + 1][k];
        float b2 = Ks[tx * 4 + 2][k];
        float b3 = Ks[tx * 4 + 3][k];
        acc[0][0] += a0 * b0; acc[0][1] += a0 * b1; acc[0][2] += a0 * b2; acc[0][3] += a0 * b3;
        acc[1][0] += a1 * b0; acc[1][1] += a1 * b1; acc[1][2] += a1 * b2; acc[1][3] += a1 * b3;
        acc[2][0] += a2 * b0; acc[2][1] += a2 * b1; acc[2][2] += a2 * b2; acc[2][3] += a2 * b3;
        acc[3][0] += a3 * b0; acc[3][1] += a3 * b1; acc[3][2] += a3 * b2; acc[3][3] += a3 * b3;
    }

    float* Pg = g_probs + ((long long)bsh << 20);
    const float* Mg = mask + ((long long)bs << 20);
#pragma unroll
    for (int i = 0; i < 4; i++) {
        int q = q0 + ty * 4 + i;
#pragma unroll
        for (int j = 0; j < 4; j++) {
            int kc = k0 + tx * 4 + j;
            Pg[q * 1024 + kc] = acc[i][j] * 0.125f + Mg[q * 1024 + kc] * (-1.0e9f);
        }
    }
}

// ---------------------------------------------------------------------------
// Row softmax in-place over g_probs (1024 per row, 262144 rows)
// ---------------------------------------------------------------------------
__global__ __launch_bounds__(256) void softmax_kernel()
{
    __shared__ float red_max[8];
    __shared__ float red_sum[8];

    const long long row = blockIdx.x;
    float* p = g_probs + row * 1024;
    const int tid  = threadIdx.x;
    const int lane = tid & 31;
    const int warp = tid >> 5;

    float4 v = ((float4*)p)[tid];
    float m = fmaxf(fmaxf(v.x, v.y), fmaxf(v.z, v.w));
#pragma unroll
    for (int o = 16; o > 0; o >>= 1)
        m = fmaxf(m, __shfl_xor_sync(0xffffffffu, m, o));
    if (lane == 0) red_max[warp] = m;
    __syncthreads();

    float rowmax = red_max[0];
#pragma unroll
    for (int i = 1; i < 8; i++) rowmax = fmaxf(rowmax, red_max[i]);

    float e0 = __expf(v.x - rowmax);
    float e1 = __expf(v.y - rowmax);
    float e2 = __expf(v.z - rowmax);
    float e3 = __expf(v.w - rowmax);
    float s = e0 + e1 + e2 + e3;
#pragma unroll
    for (int o = 16; o > 0; o >>= 1)
        s += __shfl_xor_sync(0xffffffffu, s, o);
    if (lane == 0) red_sum[warp] = s;
    __syncthreads();

    float tot = 0.f;
#pragma unroll
    for (int i = 0; i < 8; i++) tot += red_sum[i];
    float inv = __frcp_rn(tot);

    float4 o4;
    o4.x = e0 * inv; o4.y = e1 * inv; o4.z = e2 * inv; o4.w = e3 * inv;
    ((float4*)p)[tid] = o4;
}

// ---------------------------------------------------------------------------
// ctx = probs @ V per (bsh), written merged [bs*L + q][h*64 + d]
// 64x64 tile, BK=16, 256 thr, 4x4/thr
// ---------------------------------------------------------------------------
__global__ __launch_bounds__(256) void ctx_kernel()
{
    __shared__ float Ps[64][17];
    __shared__ float Vs[16][64];

    const int m0  = blockIdx.x * 64;
    const int bsh = blockIdx.y;
    const int h   = bsh & 15;
    const int bs  = bsh >> 4;

    const float* P = g_probs + ((long long)bsh << 20);
    const float* V = g_vh + (long long)bsh * 65536;

    const int tid = threadIdx.x;
    const int tx = tid & 15;
    const int ty = tid >> 4;
    const int pr  = tid >> 2;
    const int pc4 = (tid & 3) * 4;
    const int vr  = tid >> 4;
    const int vc4 = (tid & 15) * 4;

    float acc[4][4];
#pragma unroll
    for (int i = 0; i < 4; i++)
#pragma unroll
        for (int j = 0; j < 4; j++) acc[i][j] = 0.f;

    for (int k0 = 0; k0 < 1024; k0 += 16) {
        float4 pa = *(const float4*)(P + (m0 + pr) * 1024 + k0 + pc4);
        Ps[pr][pc4 + 0] = pa.x; Ps[pr][pc4 + 1] = pa.y;
        Ps[pr][pc4 + 2] = pa.z; Ps[pr][pc4 + 3] = pa.w;
        *(float4*)&Vs[vr][vc4] = *(const float4*)(V + (k0 + vr) * 64 + vc4);
        __syncthreads();

#pragma unroll
        for (int k = 0; k < 16; k++) {
            float a0 = Ps[ty * 4 + 0][k];
            float a1 = Ps[ty * 4 + 1][k];
            float a2 = Ps[ty * 4 + 2][k];
            float a3 = Ps[ty * 4 + 3][k];
            float b0 = Vs[k][tx * 4 + 0];
            float b1 = Vs[k][tx * 4 + 1];
            float b2 = Vs[k][tx * 4 + 2];
            float b3 = Vs[k][tx * 4 + 3];
            acc[0][0] += a0 * b0; acc[0][1] += a0 * b1; acc[0][2] += a0 * b2; acc[0][3] += a0 * b3;
            acc[1][0] += a1 * b0; acc[1][1] += a1 * b1; acc[1][2] += a1 * b2; acc[1][3] += a1 * b3;
            acc[2][0] += a2 * b0; acc[2][1] += a2 * b1; acc[2][2] += a2 * b2; acc[2][3] += a2 * b3;
            acc[3][0] += a3 * b0; acc[3][1] += a3 * b1; acc[3][2] += a3 * b2; acc[3][3] += a3 * b3;
        }
        __syncthreads();
    }

#pragma unroll
    for (int i = 0; i < 4; i++) {
        int q = m0 + ty * 4 + i;
        float* dst = g_ctx + ((long long)(bs * 1024 + q)) * 1024 + h * 64;
#pragma unroll
        for (int j = 0; j < 4; j++)
            dst[tx * 4 + j] = acc[i][j];
    }
}

// ---------------------------------------------------------------------------
// attn_mean = mean over heads of probs
// ---------------------------------------------------------------------------
__global__ __launch_bounds__(256) void head_mean_kernel(float* __restrict__ outm)
{
    const int i = blockIdx.x * 256 + threadIdx.x;  // < 16777216
    const int bs  = i >> 20;
    const int rem = i & 0xFFFFF;
    const float* base = g_probs + ((long long)bs << 24) + rem;
    float s = 0.f;
#pragma unroll
    for (int h = 0; h < 16; h++)
        s += base[(long long)h << 20];
    outm[i] = s * 0.0625f;
}

// ---------------------------------------------------------------------------
extern "C" void kernel_launch(void* const* d_in, const int* in_sizes, int n_in,
                              void* d_out, int out_size)
{
    const float* q    = (const float*)d_in[0];
    const float* k    = (const float*)d_in[1];
    const float* v    = (const float*)d_in[2];
    const float* mask = (const float*)d_in[3];
    const float* wq   = (const float*)d_in[4];
    const float* bq   = (const float*)d_in[5];
    const float* wk   = (const float*)d_in[6];
    const float* bk   = (const float*)d_in[7];
    const float* wv   = (const float*)d_in[8];
    const float* bv   = (const float*)d_in[9];
    const float* wo   = (const float*)d_in[10];
    const float* bo   = (const float*)d_in[11];

    float* out       = (float*)d_out;
    float* attn_mean = out + OUT_ELEMS;

    float *p_qh, *p_kh, *p_vh, *p_ctx;
    cudaGetSymbolAddress((void**)&p_qh,  g_qh);
    cudaGetSymbolAddress((void**)&p_kh,  g_kh);
    cudaGetSymbolAddress((void**)&p_vh,  g_vh);
    cudaGetSymbolAddress((void**)&p_ctx, g_ctx);

    dim3 gemmGrid(Dq / 128, MROWS / 128);   // (8, 128)

    // QKV projections (head-split outputs)
    sgemm_bias<<<gemmGrid, 256>>>(q, wq, bq, p_qh, Dq, Dq, 1);
    sgemm_bias<<<gemmGrid, 256>>>(k, wk, bk, p_kh, Dq, Dq, 1);
    sgemm_bias<<<gemmGrid, 256>>>(v, wv, bv, p_vh, Dq, Dq, 1);

    // logits (+scale+mask) -> g_probs
    qk_logits_kernel<<<dim3(16, 16, BSHq), 256>>>(mask);

    // softmax in place
    softmax_kernel<<<BSHq * Lq_, 256>>>();

    // ctx = probs @ V, merged layout
    ctx_kernel<<<dim3(16, BSHq), 256>>>();

    // attn_mean output
    head_mean_kernel<<<OUT_ELEMS / 256, 256>>>(attn_mean);

    // output projection
    sgemm_bias<<<gemmGrid, 256>>>(p_ctx, wo, bo, out, Dq, Dq, 0);
}

// round 3
// speedup vs baseline: 1.4197x; 1.4191x over previous
#include <cuda_runtime.h>
#include <cuda_bf16.h>

typedef unsigned short u16;
typedef unsigned int   u32;

#define NEGBIG (-1.0e9f)

// ---------------- device scratch (allocation-free rule) --------------------
__device__ u16 g_wt_hi[4u*1024u*1024u];   // 4 weights, transposed [n][k]
__device__ u16 g_wt_lo[4u*1024u*1024u];
__device__ u16 g_a_hi[16777216];          // activation staging (q, then k, then v, reused)
__device__ u16 g_a_lo[16777216];
__device__ u16 g_qh_hi[16777216];         // [bsh][l][64]
__device__ u16 g_qh_lo[16777216];
__device__ u16 g_kh_hi[16777216];         // [bsh][l][64]
__device__ u16 g_kh_lo[16777216];
__device__ u16 g_vt_hi[16777216];         // [bsh][d=64][l=1024]
__device__ u16 g_vt_lo[16777216];
__device__ float g_logits[268435456];     // [bsh][q][k] fp32
__device__ u16 g_p_hi[268435456];         // probs bf16 hi/lo
__device__ u16 g_p_lo[268435456];
__device__ u16 g_ctx_hi[16777216];        // merged [bs*L+q][1024]
__device__ u16 g_ctx_lo[16777216];

// ---------------- helpers --------------------------------------------------
__device__ __forceinline__ u16 f2b(float x){
    return __bfloat16_as_ushort(__float2bfloat16_rn(x));
}
__device__ __forceinline__ float b2f(u16 u){
    return __bfloat162float(__ushort_as_bfloat16(u));
}
__device__ __forceinline__ u32 pack2(float a, float b){
    return (u32)f2b(a) | ((u32)f2b(b) << 16);
}
__device__ __forceinline__ unsigned smem_u32p(const void* p){
    unsigned a;
    asm("{ .reg .u64 t; cvta.to.shared.u64 t, %1; cvt.u32.u64 %0, t; }"
        : "=r"(a) : "l"(p));
    return a;
}
__device__ __forceinline__ void ldmx4(u32& r0, u32& r1, u32& r2, u32& r3, unsigned a){
    asm volatile("ldmatrix.sync.aligned.m8n8.x4.shared.b16 {%0,%1,%2,%3}, [%4];"
                 : "=r"(r0), "=r"(r1), "=r"(r2), "=r"(r3) : "r"(a));
}
__device__ __forceinline__ void mma16816(float* c, const u32* a, u32 b0, u32 b1){
    asm volatile(
        "mma.sync.aligned.m16n8k16.row.col.f32.bf16.bf16.f32 "
        "{%0,%1,%2,%3}, {%4,%5,%6,%7}, {%8,%9}, {%0,%1,%2,%3};"
        : "+f"(c[0]), "+f"(c[1]), "+f"(c[2]), "+f"(c[3])
        : "r"(a[0]), "r"(a[1]), "r"(a[2]), "r"(a[3]), "r"(b0), "r"(b1));
}
__device__ __forceinline__ void cpa16(unsigned dst, const void* src){
    asm volatile("cp.async.cg.shared.global [%0], [%1], 16;" :: "r"(dst), "l"(src));
}
#define CPA_COMMIT() asm volatile("cp.async.commit_group;" ::: "memory")
template<int N> __device__ __forceinline__ void cpa_wait(){
    asm volatile("cp.async.wait_group %0;" :: "n"(N) : "memory");
}

// ---------------------------------------------------------------------------
// Tensor-core GEMM, bf16 hi/lo 3-pass:  D[128 x BN] = A[128,K] . B[BN,K]^T
// A and B both K-major. Epilogue modes:
//   0: fp32 row-major + bias       1: hi/lo head-split [bs][h][l][d] + bias
//   2: hi/lo V-transpose [bsh][d][l] + bias
//   3: fp32 logits = acc*0.125 + mask*NEG   4: hi/lo ctx merged [bs*L+q][1024]
// ---------------------------------------------------------------------------
template<int BN, int WGM, int WGN>
__global__ void __launch_bounds__(256) gemm_mma(
    const u16* __restrict__ Ahi, const u16* __restrict__ Alo, size_t aZ,
    const u16* __restrict__ Bhi, const u16* __restrict__ Blo, size_t bZ,
    int K, int mode,
    float* __restrict__ outF, u16* __restrict__ oHi, u16* __restrict__ oLo,
    const float* __restrict__ aux)
{
    constexpr int PITCH = 40;
    constexpr int ASZ = 128 * PITCH;       // elems
    constexpr int BSZ = BN * PITCH;
    constexpr int STAGE = 2 * ASZ + 2 * BSZ;
    constexpr int WTM = 128 / WGM;
    constexpr int WTN = BN / WGN;
    constexpr int MT = WTM / 16;
    constexpr int NT16 = WTN / 16;

    extern __shared__ u16 smem[];
    const unsigned sbase = smem_u32p(smem);

    const int tid  = threadIdx.x;
    const int w    = tid >> 5;
    const int lane = tid & 31;
    const int m0   = blockIdx.y * 128;
    const int n0   = blockIdx.x * BN;
    const int z    = blockIdx.z;

    const u16* Ah = Ahi + (size_t)z * aZ;
    const u16* Al = Alo + (size_t)z * aZ;
    const u16* Bh = Bhi + (size_t)z * bZ;
    const u16* Bl = Blo + (size_t)z * bZ;

    const int wm = (w / WGN) * WTM;
    const int wn = (w % WGN) * WTN;
    const int lrow = (lane & 7) + ((lane >> 3) & 1) * 8;
    const int lcol = (lane >> 4) * 8;

    float acc[MT][NT16 * 2][4];
#pragma unroll
    for (int i = 0; i < MT; i++)
#pragma unroll
        for (int j = 0; j < NT16 * 2; j++)
#pragma unroll
            for (int t = 0; t < 4; t++) acc[i][j][t] = 0.f;

    auto load_stage = [&](int s){
        const int k0 = s << 5;
        const unsigned sd = sbase + (unsigned)((s & 1) * STAGE) * 2u;
#pragma unroll
        for (int it = 0; it < 2; it++){
            int idx = tid + it * 256;               // 512 A chunks
            int r = idx >> 2, c = idx & 3;
            size_t g = (size_t)(m0 + r) * K + k0 + c * 8;
            unsigned d = sd + (unsigned)(r * PITCH + c * 8) * 2u;
            cpa16(d, Ah + g);
            cpa16(d + ASZ * 2, Al + g);
        }
#pragma unroll
        for (int it = 0; it < (BN * 4) / 256; it++){
            int idx = tid + it * 256;
            int r = idx >> 2, c = idx & 3;
            size_t g = (size_t)(n0 + r) * K + k0 + c * 8;
            unsigned d = sd + (unsigned)(2 * ASZ + r * PITCH + c * 8) * 2u;
            cpa16(d, Bh + g);
            cpa16(d + BSZ * 2, Bl + g);
        }
        CPA_COMMIT();
    };

    const int NS = K >> 5;
    load_stage(0);

    for (int s = 0; s < NS; s++){
        if (s + 1 < NS){ load_stage(s + 1); cpa_wait<1>(); }
        else           { cpa_wait<0>(); }
        __syncthreads();

        const unsigned sd = sbase + (unsigned)((s & 1) * STAGE) * 2u;
#pragma unroll
        for (int k16 = 0; k16 < 2; k16++){
            const int kc = k16 * 16 + lcol;
            u32 ah[MT][4], al[MT][4], bh[NT16][4], bl[NT16][4];
#pragma unroll
            for (int mt = 0; mt < MT; mt++){
                unsigned a = sd + (unsigned)((wm + mt * 16 + lrow) * PITCH + kc) * 2u;
                ldmx4(ah[mt][0], ah[mt][1], ah[mt][2], ah[mt][3], a);
                ldmx4(al[mt][0], al[mt][1], al[mt][2], al[mt][3], a + ASZ * 2);
            }
#pragma unroll
            for (int nt = 0; nt < NT16; nt++){
                unsigned a = sd + (unsigned)(2 * ASZ + (wn + nt * 16 + lrow) * PITCH + kc) * 2u;
                ldmx4(bh[nt][0], bh[nt][1], bh[nt][2], bh[nt][3], a);
                ldmx4(bl[nt][0], bl[nt][1], bl[nt][2], bl[nt][3], a + BSZ * 2);
            }
#pragma unroll
            for (int mt = 0; mt < MT; mt++)
#pragma unroll
                for (int nt = 0; nt < NT16; nt++){
                    mma16816(acc[mt][2*nt],   ah[mt], bh[nt][0], bh[nt][2]);
                    mma16816(acc[mt][2*nt+1], ah[mt], bh[nt][1], bh[nt][3]);
                    mma16816(acc[mt][2*nt],   ah[mt], bl[nt][0], bl[nt][2]);
                    mma16816(acc[mt][2*nt+1], ah[mt], bl[nt][1], bl[nt][3]);
                    mma16816(acc[mt][2*nt],   al[mt], bh[nt][0], bh[nt][2]);
                    mma16816(acc[mt][2*nt+1], al[mt], bh[nt][1], bh[nt][3]);
                }
        }
        __syncthreads();
    }

    // ---- epilogue ----
    auto store_pair = [&](int row, int col, float va, float vb){
        if (mode == 0){
            float2 o; o.x = va + aux[col]; o.y = vb + aux[col + 1];
            *(float2*)(outF + (size_t)row * 1024 + col) = o;
        } else if (mode == 1){
            va += aux[col]; vb += aux[col + 1];
            int bs = row >> 10, l = row & 1023, h = col >> 6, d = col & 63;
            size_t idx = (((size_t)(bs * 16 + h)) << 16) + ((size_t)l << 6) + d;
            *(u32*)(oHi + idx) = pack2(va, vb);
            *(u32*)(oLo + idx) = pack2(va - b2f(f2b(va)), vb - b2f(f2b(vb)));
        } else if (mode == 2){
            va += aux[col]; vb += aux[col + 1];
            int bs = row >> 10, l = row & 1023, h = col >> 6, d = col & 63;
            size_t base = ((size_t)(bs * 16 + h) * 64 + d) * 1024 + l;
            u16 h0 = f2b(va), h1 = f2b(vb);
            oHi[base] = h0;        oHi[base + 1024] = h1;
            oLo[base] = f2b(va - b2f(h0));
            oLo[base + 1024] = f2b(vb - b2f(h1));
        } else if (mode == 3){
            size_t mi = (((size_t)(z >> 4)) << 20) + ((size_t)row << 10) + col;
            float2 m2 = *(const float2*)(aux + mi);
            float2 o;
            o.x = va * 0.125f + m2.x * NEGBIG;
            o.y = vb * 0.125f + m2.y * NEGBIG;
            *(float2*)(outF + (((size_t)z << 20) + ((size_t)row << 10) + col)) = o;
        } else { // 4: ctx merged
            size_t idx = ((size_t)((z >> 4) * 1024 + row) << 10) + (size_t)(z & 15) * 64 + col;
            *(u32*)(oHi + idx) = pack2(va, vb);
            *(u32*)(oLo + idx) = pack2(va - b2f(f2b(va)), vb - b2f(f2b(vb)));
        }
    };

#pragma unroll
    for (int mt = 0; mt < MT; mt++)
#pragma unroll
        for (int nt8 = 0; nt8 < NT16 * 2; nt8++){
            int r0 = m0 + wm + mt * 16 + (lane >> 2);
            int c0 = n0 + wn + nt8 * 8 + (lane & 3) * 2;
            store_pair(r0,     c0, acc[mt][nt8][0], acc[mt][nt8][1]);
            store_pair(r0 + 8, c0, acc[mt][nt8][2], acc[mt][nt8][3]);
        }
}

// ---------------------------------------------------------------------------
// fp32 -> bf16 hi/lo (activations / ctx inputs), 4 elems per thread
// ---------------------------------------------------------------------------
__global__ __launch_bounds__(256) void conv_act(
    const float* __restrict__ in, u16* __restrict__ hi, u16* __restrict__ lo)
{
    const int i = blockIdx.x * 256 + threadIdx.x;   // per float4
    float4 v = ((const float4*)in)[i];
    u32 h0 = pack2(v.x, v.y), h1 = pack2(v.z, v.w);
    ((u32*)hi)[i * 2]     = h0;
    ((u32*)hi)[i * 2 + 1] = h1;
    ((u32*)lo)[i * 2]     = pack2(v.x - b2f((u16)h0), v.y - b2f((u16)(h0 >> 16)));
    ((u32*)lo)[i * 2 + 1] = pack2(v.z - b2f((u16)h1), v.w - b2f((u16)(h1 >> 16)));
}

// ---------------------------------------------------------------------------
// Weight transpose + convert: W[k][n] fp32 -> WT[n][k] bf16 hi/lo
// ---------------------------------------------------------------------------
__global__ __launch_bounds__(256) void conv_wT(
    const float* __restrict__ W, u16* __restrict__ hi, u16* __restrict__ lo)
{
    __shared__ float tile[32][33];
    const int tx = threadIdx.x, ty = threadIdx.y;   // (32, 8)
    const int kb = blockIdx.y * 32, nb = blockIdx.x * 32;
#pragma unroll
    for (int i = 0; i < 4; i++)
        tile[ty + i * 8][tx] = W[(size_t)(kb + ty + i * 8) * 1024 + nb + tx];
    __syncthreads();
#pragma unroll
    for (int i = 0; i < 4; i++){
        int n = nb + ty + i * 8, k = kb + tx;
        float v = tile[tx][ty + i * 8];
        u16 h = f2b(v);
        hi[(size_t)n * 1024 + k] = h;
        lo[(size_t)n * 1024 + k] = f2b(v - b2f(h));
    }
}

// ---------------------------------------------------------------------------
// Row softmax: fp32 logits -> bf16 hi/lo probs
// ---------------------------------------------------------------------------
__global__ __launch_bounds__(256) void softmax_kernel()
{
    __shared__ float red[8];
    const size_t row = blockIdx.x;
    const float* p = g_logits + row * 1024;
    const int tid = threadIdx.x, lane = tid & 31, warp = tid >> 5;

    float4 v = ((const float4*)p)[tid];
    float m = fmaxf(fmaxf(v.x, v.y), fmaxf(v.z, v.w));
#pragma unroll
    for (int o = 16; o > 0; o >>= 1) m = fmaxf(m, __shfl_xor_sync(~0u, m, o));
    if (lane == 0) red[warp] = m;
    __syncthreads();
    float rm = red[0];
#pragma unroll
    for (int i = 1; i < 8; i++) rm = fmaxf(rm, red[i]);
    __syncthreads();

    float e0 = __expf(v.x - rm), e1 = __expf(v.y - rm);
    float e2 = __expf(v.z - rm), e3 = __expf(v.w - rm);
    float s = e0 + e1 + e2 + e3;
#pragma unroll
    for (int o = 16; o > 0; o >>= 1) s += __shfl_xor_sync(~0u, s, o);
    if (lane == 0) red[warp] = s;
    __syncthreads();
    float tot = 0.f;
#pragma unroll
    for (int i = 0; i < 8; i++) tot += red[i];
    float inv = __frcp_rn(tot);

    float p0 = e0 * inv, p1 = e1 * inv, p2 = e2 * inv, p3 = e3 * inv;
    size_t o2 = row * 512 + tid * 2;
    u32 h0 = pack2(p0, p1), h1 = pack2(p2, p3);
    ((u32*)g_p_hi)[o2]     = h0;
    ((u32*)g_p_hi)[o2 + 1] = h1;
    ((u32*)g_p_lo)[o2]     = pack2(p0 - b2f((u16)h0), p1 - b2f((u16)(h0 >> 16)));
    ((u32*)g_p_lo)[o2 + 1] = pack2(p2 - b2f((u16)h1), p3 - b2f((u16)(h1 >> 16)));
}

// ---------------------------------------------------------------------------
// attn_mean over heads from bf16 hi/lo probs (2 elems per thread)
// ---------------------------------------------------------------------------
__global__ __launch_bounds__(256) void head_mean_kernel(float* __restrict__ outm)
{
    const int i = blockIdx.x * 256 + threadIdx.x;        // pair index
    const int elem = i * 2;
    const int bs = elem >> 20, rem = elem & 0xFFFFF;
    float s0 = 0.f, s1 = 0.f;
#pragma unroll
    for (int h = 0; h < 16; h++){
        size_t u = ((size_t)((bs * 16 + h)) << 19) + (rem >> 1);
        u32 uh = ((const u32*)g_p_hi)[u];
        u32 ul = ((const u32*)g_p_lo)[u];
        s0 += b2f((u16)uh) + b2f((u16)ul);
        s1 += b2f((u16)(uh >> 16)) + b2f((u16)(ul >> 16));
    }
    float2 o; o.x = s0 * 0.0625f; o.y = s1 * 0.0625f;
    *(float2*)(outm + elem) = o;
}

// ---------------------------------------------------------------------------
extern "C" void kernel_launch(void* const* d_in, const int* in_sizes, int n_in,
                              void* d_out, int out_size)
{
    const float* q    = (const float*)d_in[0];
    const float* k    = (const float*)d_in[1];
    const float* v    = (const float*)d_in[2];
    const float* mask = (const float*)d_in[3];
    const float* wq   = (const float*)d_in[4];
    const float* bq   = (const float*)d_in[5];
    const float* wk   = (const float*)d_in[6];
    const float* bk   = (const float*)d_in[7];
    const float* wv   = (const float*)d_in[8];
    const float* bv   = (const float*)d_in[9];
    const float* wo   = (const float*)d_in[10];
    const float* bo   = (const float*)d_in[11];

    float* out       = (float*)d_out;
    float* attn_mean = out + 16777216;

    u16 *wtH, *wtL, *aH, *aL, *qhH, *qhL, *khH, *khL, *vtH, *vtL, *pH, *pL, *cxH, *cxL;
    float* lg;
    cudaGetSymbolAddress((void**)&wtH, g_wt_hi);
    cudaGetSymbolAddress((void**)&wtL, g_wt_lo);
    cudaGetSymbolAddress((void**)&aH,  g_a_hi);
    cudaGetSymbolAddress((void**)&aL,  g_a_lo);
    cudaGetSymbolAddress((void**)&qhH, g_qh_hi);
    cudaGetSymbolAddress((void**)&qhL, g_qh_lo);
    cudaGetSymbolAddress((void**)&khH, g_kh_hi);
    cudaGetSymbolAddress((void**)&khL, g_kh_lo);
    cudaGetSymbolAddress((void**)&vtH, g_vt_hi);
    cudaGetSymbolAddress((void**)&vtL, g_vt_lo);
    cudaGetSymbolAddress((void**)&pH,  g_p_hi);
    cudaGetSymbolAddress((void**)&pL,  g_p_lo);
    cudaGetSymbolAddress((void**)&cxH, g_ctx_hi);
    cudaGetSymbolAddress((void**)&cxL, g_ctx_lo);
    cudaGetSymbolAddress((void**)&lg,  g_logits);

    constexpr int SMEM_BIG   = (2 * (2 * 128 * 40 + 2 * 128 * 40)) * 2;  // 81920 B
    constexpr int SMEM_SMALL = (2 * (2 * 128 * 40 + 2 * 64 * 40)) * 2;   // 61440 B
    cudaFuncSetAttribute(gemm_mma<128,2,4>,
                         cudaFuncAttributeMaxDynamicSharedMemorySize, SMEM_BIG);
    cudaFuncSetAttribute(gemm_mma<64,4,2>,
                         cudaFuncAttributeMaxDynamicSharedMemorySize, SMEM_SMALL);

    dim3 wtg(32, 32);
    dim3 wtb(32, 8);
    conv_wT<<<wtg, wtb>>>(wq, wtH + 0u,       wtL + 0u);
    conv_wT<<<wtg, wtb>>>(wk, wtH + 1048576u, wtL + 1048576u);
    conv_wT<<<wtg, wtb>>>(wv, wtH + 2097152u, wtL + 2097152u);
    conv_wT<<<wtg, wtb>>>(wo, wtH + 3145728u, wtL + 3145728u);

    dim3 projGrid(8, 128, 1);

    // Q projection -> head-split
    conv_act<<<16384, 256>>>(q, aH, aL);
    gemm_mma<128,2,4><<<projGrid, 256, SMEM_BIG>>>(
        aH, aL, 0, wtH + 0u, wtL + 0u, 0, 1024, 1, nullptr, qhH, qhL, bq);
    // K projection
    conv_act<<<16384, 256>>>(k, aH, aL);
    gemm_mma<128,2,4><<<projGrid, 256, SMEM_BIG>>>(
        aH, aL, 0, wtH + 1048576u, wtL + 1048576u, 0, 1024, 1, nullptr, khH, khL, bk);
    // V projection -> transposed [bsh][d][l]
    conv_act<<<16384, 256>>>(v, aH, aL);
    gemm_mma<128,2,4><<<projGrid, 256, SMEM_BIG>>>(
        aH, aL, 0, wtH + 2097152u, wtL + 2097152u, 0, 1024, 2, nullptr, vtH, vtL, bv);

    // QK^T logits (scale + mask fused)
    gemm_mma<128,2,4><<<dim3(8, 8, 256), 256, SMEM_BIG>>>(
        qhH, qhL, 65536, khH, khL, 65536, 64, 3, lg, nullptr, nullptr, mask);

    // softmax -> bf16 hi/lo probs
    softmax_kernel<<<262144, 256>>>();

    // ctx = P @ V  (A = probs [q][k], B = vt [d][l])
    gemm_mma<64,4,2><<<dim3(1, 8, 256), 256, SMEM_SMALL>>>(
        pH, pL, (size_t)1 << 20, vtH, vtL, 65536, 1024, 4, nullptr, cxH, cxL, nullptr);

    // attn_mean
    head_mean_kernel<<<32768, 256>>>(attn_mean);

    // out projection (fp32 out + bias)
    gemm_mma<128,2,4><<<projGrid, 256, SMEM_BIG>>>(
        cxH, cxL, 0, wtH + 3145728u, wtL + 3145728u, 0, 1024, 0, out, nullptr, nullptr, bo);
}

// round 7
// speedup vs baseline: 2.1041x; 1.4821x over previous
#include <cuda_runtime.h>
#include <cuda_bf16.h>

typedef unsigned short u16;
typedef unsigned int   u32;
typedef unsigned long long u64;

#define NEGBIG (-1.0e9f)

#if defined(__CUDA_ARCH_FEAT_SM103_ALL) || defined(__CUDA_ARCH_FEAT_SM100_ALL)
#define HAS_TCGEN05 1
#else
#define HAS_TCGEN05 0
#endif

// ---------------- device scratch (allocation-free rule) --------------------
__device__ u16 g_wt_hi[4u*1024u*1024u];   // 4 weights, transposed [n][k]
__device__ u16 g_wt_lo[4u*1024u*1024u];
__device__ u16 g_a_hi[16777216];          // activation staging (reused q,k,v)
__device__ u16 g_a_lo[16777216];
__device__ u16 g_qh_hi[16777216];         // [bsh][l][64]
__device__ u16 g_qh_lo[16777216];
__device__ u16 g_kh_hi[16777216];
__device__ u16 g_kh_lo[16777216];
__device__ u16 g_vt_hi[16777216];         // [bsh][d=64][l=1024]
__device__ u16 g_vt_lo[16777216];
__device__ float g_logits[268435456];     // [bsh][q][k] fp32
__device__ u16 g_p_hi[268435456];         // probs bf16 hi/lo
__device__ u16 g_p_lo[268435456];
__device__ u16 g_ctx_hi[16777216];        // merged [bs*L+q][1024]
__device__ u16 g_ctx_lo[16777216];

// ---------------- helpers --------------------------------------------------
__device__ __forceinline__ u16 f2b(float x){
    return __bfloat16_as_ushort(__float2bfloat16_rn(x));
}
__device__ __forceinline__ float b2f(u16 u){
    return __bfloat162float(__ushort_as_bfloat16(u));
}
__device__ __forceinline__ u32 pack2(float a, float b){
    return (u32)f2b(a) | ((u32)f2b(b) << 16);
}
__device__ __forceinline__ unsigned smem_u32p(const void* p){
    unsigned a;
    asm("{ .reg .u64 t; cvta.to.shared.u64 t, %1; cvt.u32.u64 %0, t; }"
        : "=r"(a) : "l"(p));
    return a;
}
__device__ __forceinline__ void cpa16(unsigned dst, const void* src){
    asm volatile("cp.async.cg.shared.global [%0], [%1], 16;" :: "r"(dst), "l"(src));
}
#define CPA_COMMIT() asm volatile("cp.async.commit_group;" ::: "memory")
template<int N> __device__ __forceinline__ void cpa_wait(){
    asm volatile("cp.async.wait_group %0;" :: "n"(N) : "memory");
}

#if HAS_TCGEN05
__device__ __forceinline__ unsigned elect1(){
    unsigned p;
    asm volatile("{ .reg .pred P; elect.sync _|P, 0xFFFFFFFF; selp.b32 %0, 1, 0, P; }"
                 : "=r"(p));
    return p;
}
#define MBAR_INIT(a, c) \
    asm volatile("mbarrier.init.shared.b64 [%0], %1;" :: "r"(a), "r"(c) : "memory")
#define MBAR_INVAL(a) \
    asm volatile("mbarrier.inval.shared.b64 [%0];" :: "r"(a) : "memory")
__device__ __forceinline__ void mbar_wait(unsigned a, unsigned ph){
    asm volatile(
        "{\n\t.reg .pred P;\n"
        "W%=:\n\t"
        "mbarrier.try_wait.parity.acquire.cta.shared::cta.b64 P, [%0], %1, 0x989680;\n\t"
        "@P bra D%=;\n\t"
        "bra W%=;\n"
        "D%=:\n\t}"
        :: "r"(a), "r"(ph) : "memory");
}
#define TC_ALLOC(sa, n) \
    asm volatile("tcgen05.alloc.cta_group::1.sync.aligned.shared::cta.b32 [%0], %1;" \
                 :: "r"(sa), "r"(n) : "memory")
#define TC_DEALLOC(t, n) \
    asm volatile("tcgen05.dealloc.cta_group::1.sync.aligned.b32 %0, %1;" :: "r"(t), "r"(n))
#define TC_COMMIT(mb) \
    asm volatile("tcgen05.commit.cta_group::1.mbarrier::arrive::one.shared::cluster.b64 [%0];" \
                 :: "r"(mb) : "memory")
#define TC_FENCE_AFTER()  asm volatile("tcgen05.fence::after_thread_sync;" ::: "memory")
#define TC_FENCE_BEFORE() asm volatile("tcgen05.fence::before_thread_sync;" ::: "memory")
#define TC_WAITLD()       asm volatile("tcgen05.wait::ld.sync.aligned;" ::: "memory")
#define FENCE_ASYNC()     asm volatile("fence.proxy.async.shared::cta;" ::: "memory")

#define TC_LD32(r, addr) \
    asm volatile( \
        "tcgen05.ld.sync.aligned.32x32b.x32.b32 " \
        "{%0, %1, %2, %3, %4, %5, %6, %7, " \
        " %8, %9, %10, %11, %12, %13, %14, %15, " \
        " %16, %17, %18, %19, %20, %21, %22, %23, " \
        " %24, %25, %26, %27, %28, %29, %30, %31}, [%32];" \
        : "=r"((r)[0]),  "=r"((r)[1]),  "=r"((r)[2]),  "=r"((r)[3]), \
          "=r"((r)[4]),  "=r"((r)[5]),  "=r"((r)[6]),  "=r"((r)[7]), \
          "=r"((r)[8]),  "=r"((r)[9]),  "=r"((r)[10]), "=r"((r)[11]), \
          "=r"((r)[12]), "=r"((r)[13]), "=r"((r)[14]), "=r"((r)[15]), \
          "=r"((r)[16]), "=r"((r)[17]), "=r"((r)[18]), "=r"((r)[19]), \
          "=r"((r)[20]), "=r"((r)[21]), "=r"((r)[22]), "=r"((r)[23]), \
          "=r"((r)[24]), "=r"((r)[25]), "=r"((r)[26]), "=r"((r)[27]), \
          "=r"((r)[28]), "=r"((r)[29]), "=r"((r)[30]), "=r"((r)[31]) \
        : "r"(addr))

// SW128 K-major descriptor (LBO=1, SBO=64, version=1, layout=SW128)
__device__ __forceinline__ u64 mk_desc(unsigned addr){
    const u64 base = (2ull << 61) | (1ull << 46) | (64ull << 32) | (1ull << 16);
    return base | ((u64)(addr >> 4) & 0x3FFFull);
}
__device__ __forceinline__ void mma_ss(unsigned d, u64 a, u64 b, u32 idesc, u32 en){
    asm volatile(
        "{\n\t.reg .pred p;\n\t"
        "setp.ne.u32 p, %4, 0;\n\t"
        "tcgen05.mma.cta_group::1.kind::f16 [%0], %1, %2, %3, {%5, %5, %5, %5}, p;\n\t}"
        :: "r"(d), "l"(a), "l"(b), "r"(idesc), "r"(en), "r"(0u) : "memory");
}
#else
__device__ __forceinline__ void ldmx4(u32& r0, u32& r1, u32& r2, u32& r3, unsigned a){
    asm volatile("ldmatrix.sync.aligned.m8n8.x4.shared.b16 {%0,%1,%2,%3}, [%4];"
                 : "=r"(r0), "=r"(r1), "=r"(r2), "=r"(r3) : "r"(a));
}
__device__ __forceinline__ void mma16816(float* c, const u32* a, u32 b0, u32 b1){
    asm volatile(
        "mma.sync.aligned.m16n8k16.row.col.f32.bf16.bf16.f32 "
        "{%0,%1,%2,%3}, {%4,%5,%6,%7}, {%8,%9}, {%0,%1,%2,%3};"
        : "+f"(c[0]), "+f"(c[1]), "+f"(c[2]), "+f"(c[3])
        : "r"(a[0]), "r"(a[1]), "r"(a[2]), "r"(a[3]), "r"(b0), "r"(b1));
}
#endif

// ---------------------------------------------------------------------------
// GEMM, bf16 hi/lo 3-pass:  D[128 x BN] = A[128,K] . B[BN,K]^T
// A,B K-major bf16 hi/lo. Epilogue modes:
//   0: fp32 row-major + bias          1: hi/lo head-split [bs][h][l][d] + bias
//   2: hi/lo V-transpose [bsh][d][l] + bias
//   3: fp32 logits = acc*0.125 + mask*NEG     4: hi/lo ctx merged [bs*L+q][1024]
// tcgen05 path on sm_103a; mma.sync fallback otherwise (identical numerics).
// ---------------------------------------------------------------------------
template<int BN>
__global__ void __launch_bounds__(256) gemm_any(
    const u16* __restrict__ Ahi, const u16* __restrict__ Alo, size_t aZ,
    const u16* __restrict__ Bhi, const u16* __restrict__ Blo, size_t bZ,
    int K, int mode,
    float* __restrict__ outF, u16* __restrict__ oHi, u16* __restrict__ oLo,
    const float* __restrict__ aux)
{
    extern __shared__ char smem[];
    const int tid  = threadIdx.x;
    const int w    = tid >> 5;
    const int lane = tid & 31;
    const int m0   = blockIdx.y * 128;
    const int n0   = blockIdx.x * BN;
    const int z    = blockIdx.z;

    const u16* Ah = Ahi + (size_t)z * aZ;
    const u16* Al = Alo + (size_t)z * aZ;
    const u16* Bh = Bhi + (size_t)z * bZ;
    const u16* Bl = Blo + (size_t)z * bZ;

#if HAS_TCGEN05
    // ====================== tcgen05 path (sm_103a) =========================
    constexpr int ABYT  = 128 * 128;
    constexpr int BBYT  = BN * 128;
    constexpr int STAGE = 2 * ABYT + 2 * BBYT;
    constexpr u32 IDESC =
        (1u << 4) | (1u << 7) | (1u << 10) | ((u32)(BN / 8) << 17) | (8u << 24);
    constexpr int TCOLS = BN;

    const unsigned sb   = smem_u32p(smem);
    const unsigned mb0  = sb + 8;
    const unsigned mb1  = sb + 16;
    const unsigned buf0 = sb + 1024;

    if (w == 0){ TC_ALLOC(sb, TCOLS); }          // warp 0 only; no relinquish
    if (tid == 0){ MBAR_INIT(mb0, 1); MBAR_INIT(mb1, 1); }
    __syncthreads();
    unsigned tmem;
    asm volatile("ld.shared.b32 %0, [%1];" : "=r"(tmem) : "r"(sb));

    const int NS = K >> 6;

    auto load_stage = [&](int s){
        const unsigned bb = buf0 + (unsigned)(s & 1) * STAGE;
        const int k0 = s << 6;
#pragma unroll
        for (int it = 0; it < 4; it++){
            int idx = tid + it * 256;
            int r = idx >> 3, c = idx & 7;
            int off = r * 128 + c * 16;
            unsigned sw = (unsigned)(off ^ ((off >> 3) & 0x70));
            size_t g = (size_t)(m0 + r) * K + k0 + c * 8;
            cpa16(bb + sw,        Ah + g);
            cpa16(bb + ABYT + sw, Al + g);
        }
#pragma unroll
        for (int it = 0; it < (BN * 8) / 256; it++){
            int idx = tid + it * 256;
            int r = idx >> 3, c = idx & 7;
            int off = r * 128 + c * 16;
            unsigned sw = (unsigned)(off ^ ((off >> 3) & 0x70));
            size_t g = (size_t)(n0 + r) * K + k0 + c * 8;
            cpa16(bb + 2 * ABYT + sw,        Bh + g);
            cpa16(bb + 2 * ABYT + BBYT + sw, Bl + g);
        }
        CPA_COMMIT();
    };

    load_stage(0);
    if (NS > 1) load_stage(1);
    unsigned ph0 = 0, ph1 = 0;

    for (int s = 0; s < NS; s++){
        if (s == NS - 1) cpa_wait<0>(); else cpa_wait<1>();
        __syncthreads();

        if (w == 0 && elect1()){
            FENCE_ASYNC();
            const unsigned bb = buf0 + (unsigned)(s & 1) * STAGE;
            u64 ah = mk_desc(bb);
            u64 al = mk_desc(bb + ABYT);
            u64 bh = mk_desc(bb + 2 * ABYT);
            u64 bl = mk_desc(bb + 2 * ABYT + BBYT);
#pragma unroll
            for (int ks = 0; ks < 4; ks++)
                mma_ss(tmem, ah + 2 * ks, bh + 2 * ks, IDESC,
                       (s > 0 || ks > 0) ? 1u : 0u);
#pragma unroll
            for (int ks = 0; ks < 4; ks++)
                mma_ss(tmem, ah + 2 * ks, bl + 2 * ks, IDESC, 1u);
#pragma unroll
            for (int ks = 0; ks < 4; ks++)
                mma_ss(tmem, al + 2 * ks, bh + 2 * ks, IDESC, 1u);
            TC_COMMIT((s & 1) ? mb1 : mb0);
        }

        if (s + 2 < NS){
            if (s & 1){ mbar_wait(mb1, ph1); ph1 ^= 1; }
            else      { mbar_wait(mb0, ph0); ph0 ^= 1; }
            load_stage(s + 2);
        }
    }
    if ((NS - 1) & 1) mbar_wait(mb1, ph1);
    else              mbar_wait(mb0, ph0);
    TC_FENCE_AFTER();

    const int sub = w & 3;
    const int cb  = (BN == 128) ? (w >> 2) * 64 : 0;
    if (BN == 128 || w < 4){
        u32 dr[64];
        TC_LD32(dr,      tmem + cb);
        TC_LD32(dr + 32, tmem + cb + 32);
        TC_WAITLD();
        TC_FENCE_BEFORE();

        const int row = m0 + sub * 32 + lane;

        if (mode == 0){
            float* dst = outF + (size_t)row * 1024 + n0 + cb;
            const float* bias = aux + n0 + cb;
#pragma unroll
            for (int j = 0; j < 16; j++){
                float4 o;
                o.x = __uint_as_float(dr[j*4+0]) + bias[j*4+0];
                o.y = __uint_as_float(dr[j*4+1]) + bias[j*4+1];
                o.z = __uint_as_float(dr[j*4+2]) + bias[j*4+2];
                o.w = __uint_as_float(dr[j*4+3]) + bias[j*4+3];
                *(float4*)(dst + j*4) = o;
            }
        } else if (mode == 1){
            const int bs = row >> 10, l = row & 1023;
            const int h  = (n0 + cb) >> 6;
            const size_t base = (((size_t)(bs * 16 + h)) << 16) + ((size_t)l << 6);
            const float* bias = aux + n0 + cb;
#pragma unroll
            for (int j = 0; j < 32; j++){
                float va = __uint_as_float(dr[2*j])   + bias[2*j];
                float vb = __uint_as_float(dr[2*j+1]) + bias[2*j+1];
                *(u32*)(oHi + base + 2*j) = pack2(va, vb);
                *(u32*)(oLo + base + 2*j) =
                    pack2(va - b2f(f2b(va)), vb - b2f(f2b(vb)));
            }
        } else if (mode == 2){
            const int bs = row >> 10, l = row & 1023;
            const int h  = (n0 + cb) >> 6;
            const size_t base = ((size_t)(bs * 16 + h) * 64) * 1024 + l;
            const float* bias = aux + n0 + cb;
#pragma unroll
            for (int j = 0; j < 64; j++){
                float va = __uint_as_float(dr[j]) + bias[j];
                u16 hh = f2b(va);
                oHi[base + (size_t)j * 1024] = hh;
                oLo[base + (size_t)j * 1024] = f2b(va - b2f(hh));
            }
        } else if (mode == 3){
            const size_t mi = (((size_t)(z >> 4)) << 20) + ((size_t)row << 10) + n0 + cb;
            float* dst = outF + ((size_t)z << 20) + ((size_t)row << 10) + n0 + cb;
#pragma unroll
            for (int j = 0; j < 32; j++){
                float2 m2 = *(const float2*)(aux + mi + 2*j);
                float2 o;
                o.x = __uint_as_float(dr[2*j])   * 0.125f + m2.x * NEGBIG;
                o.y = __uint_as_float(dr[2*j+1]) * 0.125f + m2.y * NEGBIG;
                *(float2*)(dst + 2*j) = o;
            }
        } else {
            const size_t base =
                ((size_t)((z >> 4) * 1024 + row) << 10) + (size_t)(z & 15) * 64;
#pragma unroll
            for (int j = 0; j < 32; j++){
                float va = __uint_as_float(dr[2*j]);
                float vb = __uint_as_float(dr[2*j+1]);
                *(u32*)(oHi + base + 2*j) = pack2(va, vb);
                *(u32*)(oLo + base + 2*j) =
                    pack2(va - b2f(f2b(va)), vb - b2f(f2b(vb)));
            }
        }
    }
    __syncthreads();
    if (tid == 0){ MBAR_INVAL(mb0); MBAR_INVAL(mb1); }
    __syncthreads();
    if (w == 0) TC_DEALLOC(tmem, TCOLS);

#else
    // ====================== mma.sync fallback (R3-proven) ==================
    constexpr int WGM = (BN == 128) ? 2 : 4;
    constexpr int WGN = (BN == 128) ? 4 : 2;
    constexpr int PITCH = 40;
    constexpr int ASZ = 128 * PITCH;
    constexpr int BSZ = BN * PITCH;
    constexpr int STAGE = 2 * ASZ + 2 * BSZ;
    constexpr int WTM = 128 / WGM;
    constexpr int WTN = BN / WGN;
    constexpr int MT = WTM / 16;
    constexpr int NT16 = WTN / 16;

    const unsigned sbase = smem_u32p(smem);

    const int wm = (w / WGN) * WTM;
    const int wn = (w % WGN) * WTN;
    const int lrow = (lane & 7) + ((lane >> 3) & 1) * 8;
    const int lcol = (lane >> 4) * 8;

    float acc[MT][NT16 * 2][4];
#pragma unroll
    for (int i = 0; i < MT; i++)
#pragma unroll
        for (int j = 0; j < NT16 * 2; j++)
#pragma unroll
            for (int t = 0; t < 4; t++) acc[i][j][t] = 0.f;

    auto load_stage = [&](int s){
        const int k0 = s << 5;
        const unsigned sd = sbase + (unsigned)((s & 1) * STAGE) * 2u;
#pragma unroll
        for (int it = 0; it < 2; it++){
            int idx = tid + it * 256;
            int r = idx >> 2, c = idx & 3;
            size_t g = (size_t)(m0 + r) * K + k0 + c * 8;
            unsigned d = sd + (unsigned)(r * PITCH + c * 8) * 2u;
            cpa16(d, Ah + g);
            cpa16(d + ASZ * 2, Al + g);
        }
#pragma unroll
        for (int it = 0; it < (BN * 4) / 256; it++){
            int idx = tid + it * 256;
            int r = idx >> 2, c = idx & 3;
            size_t g = (size_t)(n0 + r) * K + k0 + c * 8;
            unsigned d = sd + (unsigned)(2 * ASZ + r * PITCH + c * 8) * 2u;
            cpa16(d, Bh + g);
            cpa16(d + BSZ * 2, Bl + g);
        }
        CPA_COMMIT();
    };

    const int NS = K >> 5;
    load_stage(0);

    for (int s = 0; s < NS; s++){
        if (s + 1 < NS){ load_stage(s + 1); cpa_wait<1>(); }
        else           { cpa_wait<0>(); }
        __syncthreads();

        const unsigned sd = sbase + (unsigned)((s & 1) * STAGE) * 2u;
#pragma unroll
        for (int k16 = 0; k16 < 2; k16++){
            const int kc = k16 * 16 + lcol;
            u32 ah[MT][4], al[MT][4], bh[NT16][4], bl[NT16][4];
#pragma unroll
            for (int mt = 0; mt < MT; mt++){
                unsigned a = sd + (unsigned)((wm + mt * 16 + lrow) * PITCH + kc) * 2u;
                ldmx4(ah[mt][0], ah[mt][1], ah[mt][2], ah[mt][3], a);
                ldmx4(al[mt][0], al[mt][1], al[mt][2], al[mt][3], a + ASZ * 2);
            }
#pragma unroll
            for (int nt = 0; nt < NT16; nt++){
                unsigned a = sd + (unsigned)(2 * ASZ + (wn + nt * 16 + lrow) * PITCH + kc) * 2u;
                ldmx4(bh[nt][0], bh[nt][1], bh[nt][2], bh[nt][3], a);
                ldmx4(bl[nt][0], bl[nt][1], bl[nt][2], bl[nt][3], a + BSZ * 2);
            }
#pragma unroll
            for (int mt = 0; mt < MT; mt++)
#pragma unroll
                for (int nt = 0; nt < NT16; nt++){
                    mma16816(acc[mt][2*nt],   ah[mt], bh[nt][0], bh[nt][2]);
                    mma16816(acc[mt][2*nt+1], ah[mt], bh[nt][1], bh[nt][3]);
                    mma16816(acc[mt][2*nt],   ah[mt], bl[nt][0], bl[nt][2]);
                    mma16816(acc[mt][2*nt+1], ah[mt], bl[nt][1], bl[nt][3]);
                    mma16816(acc[mt][2*nt],   al[mt], bh[nt][0], bh[nt][2]);
                    mma16816(acc[mt][2*nt+1], al[mt], bh[nt][1], bh[nt][3]);
                }
        }
        __syncthreads();
    }

    auto store_pair = [&](int row, int col, float va, float vb){
        if (mode == 0){
            float2 o; o.x = va + aux[col]; o.y = vb + aux[col + 1];
            *(float2*)(outF + (size_t)row * 1024 + col) = o;
        } else if (mode == 1){
            va += aux[col]; vb += aux[col + 1];
            int bs = row >> 10, l = row & 1023, h = col >> 6, d = col & 63;
            size_t idx = (((size_t)(bs * 16 + h)) << 16) + ((size_t)l << 6) + d;
            *(u32*)(oHi + idx) = pack2(va, vb);
            *(u32*)(oLo + idx) = pack2(va - b2f(f2b(va)), vb - b2f(f2b(vb)));
        } else if (mode == 2){
            va += aux[col]; vb += aux[col + 1];
            int bs = row >> 10, l = row & 1023, h = col >> 6, d = col & 63;
            size_t base = ((size_t)(bs * 16 + h) * 64 + d) * 1024 + l;
            u16 h0 = f2b(va), h1 = f2b(vb);
            oHi[base] = h0;        oHi[base + 1024] = h1;
            oLo[base] = f2b(va - b2f(h0));
            oLo[base + 1024] = f2b(vb - b2f(h1));
        } else if (mode == 3){
            size_t mi = (((size_t)(z >> 4)) << 20) + ((size_t)row << 10) + col;
            float2 m2 = *(const float2*)(aux + mi);
            float2 o;
            o.x = va * 0.125f + m2.x * NEGBIG;
            o.y = vb * 0.125f + m2.y * NEGBIG;
            *(float2*)(outF + (((size_t)z << 20) + ((size_t)row << 10) + col)) = o;
        } else {
            size_t idx = ((size_t)((z >> 4) * 1024 + row) << 10) + (size_t)(z & 15) * 64 + col;
            *(u32*)(oHi + idx) = pack2(va, vb);
            *(u32*)(oLo + idx) = pack2(va - b2f(f2b(va)), vb - b2f(f2b(vb)));
        }
    };

#pragma unroll
    for (int mt = 0; mt < MT; mt++)
#pragma unroll
        for (int nt8 = 0; nt8 < NT16 * 2; nt8++){
            int r0 = m0 + wm + mt * 16 + (lane >> 2);
            int c0 = n0 + wn + nt8 * 8 + (lane & 3) * 2;
            store_pair(r0,     c0, acc[mt][nt8][0], acc[mt][nt8][1]);
            store_pair(r0 + 8, c0, acc[mt][nt8][2], acc[mt][nt8][3]);
        }
#endif
}

// ---------------------------------------------------------------------------
// fp32 -> bf16 hi/lo
// ---------------------------------------------------------------------------
__global__ __launch_bounds__(256) void conv_act(
    const float* __restrict__ in, u16* __restrict__ hi, u16* __restrict__ lo)
{
    const int i = blockIdx.x * 256 + threadIdx.x;
    float4 v = ((const float4*)in)[i];
    u32 h0 = pack2(v.x, v.y), h1 = pack2(v.z, v.w);
    ((u32*)hi)[i * 2]     = h0;
    ((u32*)hi)[i * 2 + 1] = h1;
    ((u32*)lo)[i * 2]     = pack2(v.x - b2f((u16)h0), v.y - b2f((u16)(h0 >> 16)));
    ((u32*)lo)[i * 2 + 1] = pack2(v.z - b2f((u16)h1), v.w - b2f((u16)(h1 >> 16)));
}

// ---------------------------------------------------------------------------
// W[k][n] fp32 -> WT[n][k] bf16 hi/lo
// ---------------------------------------------------------------------------
__global__ __launch_bounds__(256) void conv_wT(
    const float* __restrict__ W, u16* __restrict__ hi, u16* __restrict__ lo)
{
    __shared__ float tile[32][33];
    const int tx = threadIdx.x, ty = threadIdx.y;
    const int kb = blockIdx.y * 32, nb = blockIdx.x * 32;
#pragma unroll
    for (int i = 0; i < 4; i++)
        tile[ty + i * 8][tx] = W[(size_t)(kb + ty + i * 8) * 1024 + nb + tx];
    __syncthreads();
#pragma unroll
    for (int i = 0; i < 4; i++){
        int n = nb + ty + i * 8, k = kb + tx;
        float v = tile[tx][ty + i * 8];
        u16 h = f2b(v);
        hi[(size_t)n * 1024 + k] = h;
        lo[(size_t)n * 1024 + k] = f2b(v - b2f(h));
    }
}

// ---------------------------------------------------------------------------
// Row softmax: fp32 logits -> bf16 hi/lo probs
// ---------------------------------------------------------------------------
__global__ __launch_bounds__(256) void softmax_kernel()
{
    __shared__ float red[8];
    const size_t row = blockIdx.x;
    const float* p = g_logits + row * 1024;
    const int tid = threadIdx.x, lane = tid & 31, warp = tid >> 5;

    float4 v = ((const float4*)p)[tid];
    float m = fmaxf(fmaxf(v.x, v.y), fmaxf(v.z, v.w));
#pragma unroll
    for (int o = 16; o > 0; o >>= 1) m = fmaxf(m, __shfl_xor_sync(~0u, m, o));
    if (lane == 0) red[warp] = m;
    __syncthreads();
    float rm = red[0];
#pragma unroll
    for (int i = 1; i < 8; i++) rm = fmaxf(rm, red[i]);
    __syncthreads();

    float e0 = __expf(v.x - rm), e1 = __expf(v.y - rm);
    float e2 = __expf(v.z - rm), e3 = __expf(v.w - rm);
    float s = e0 + e1 + e2 + e3;
#pragma unroll
    for (int o = 16; o > 0; o >>= 1) s += __shfl_xor_sync(~0u, s, o);
    if (lane == 0) red[warp] = s;
    __syncthreads();
    float tot = 0.f;
#pragma unroll
    for (int i = 0; i < 8; i++) tot += red[i];
    float inv = __frcp_rn(tot);

    float p0 = e0 * inv, p1 = e1 * inv, p2 = e2 * inv, p3 = e3 * inv;
    size_t o2 = row * 512 + tid * 2;
    u32 h0 = pack2(p0, p1), h1 = pack2(p2, p3);
    ((u32*)g_p_hi)[o2]     = h0;
    ((u32*)g_p_hi)[o2 + 1] = h1;
    ((u32*)g_p_lo)[o2]     = pack2(p0 - b2f((u16)h0), p1 - b2f((u16)(h0 >> 16)));
    ((u32*)g_p_lo)[o2 + 1] = pack2(p2 - b2f((u16)h1), p3 - b2f((u16)(h1 >> 16)));
}

// ---------------------------------------------------------------------------
// attn_mean over heads
// ---------------------------------------------------------------------------
__global__ __launch_bounds__(256) void head_mean_kernel(float* __restrict__ outm)
{
    const int i = blockIdx.x * 256 + threadIdx.x;
    const int elem = i * 2;
    const int bs = elem >> 20, rem = elem & 0xFFFFF;
    float s0 = 0.f, s1 = 0.f;
#pragma unroll
    for (int h = 0; h < 16; h++){
        size_t u = ((size_t)((bs * 16 + h)) << 19) + (rem >> 1);
        u32 uh = ((const u32*)g_p_hi)[u];
        u32 ul = ((const u32*)g_p_lo)[u];
        s0 += b2f((u16)uh) + b2f((u16)ul);
        s1 += b2f((u16)(uh >> 16)) + b2f((u16)(ul >> 16));
    }
    float2 o; o.x = s0 * 0.0625f; o.y = s1 * 0.0625f;
    *(float2*)(outm + elem) = o;
}

// ---------------------------------------------------------------------------
extern "C" void kernel_launch(void* const* d_in, const int* in_sizes, int n_in,
                              void* d_out, int out_size)
{
    const float* q    = (const float*)d_in[0];
    const float* k    = (const float*)d_in[1];
    const float* v    = (const float*)d_in[2];
    const float* mask = (const float*)d_in[3];
    const float* wq   = (const float*)d_in[4];
    const float* bq   = (const float*)d_in[5];
    const float* wk   = (const float*)d_in[6];
    const float* bk   = (const float*)d_in[7];
    const float* wv   = (const float*)d_in[8];
    const float* bv   = (const float*)d_in[9];
    const float* wo   = (const float*)d_in[10];
    const float* bo   = (const float*)d_in[11];

    float* out       = (float*)d_out;
    float* attn_mean = out + 16777216;

    u16 *wtH, *wtL, *aH, *aL, *qhH, *qhL, *khH, *khL, *vtH, *vtL, *pH, *pL, *cxH, *cxL;
    float* lg;
    cudaGetSymbolAddress((void**)&wtH, g_wt_hi);
    cudaGetSymbolAddress((void**)&wtL, g_wt_lo);
    cudaGetSymbolAddress((void**)&aH,  g_a_hi);
    cudaGetSymbolAddress((void**)&aL,  g_a_lo);
    cudaGetSymbolAddress((void**)&qhH, g_qh_hi);
    cudaGetSymbolAddress((void**)&qhL, g_qh_lo);
    cudaGetSymbolAddress((void**)&khH, g_kh_hi);
    cudaGetSymbolAddress((void**)&khL, g_kh_lo);
    cudaGetSymbolAddress((void**)&vtH, g_vt_hi);
    cudaGetSymbolAddress((void**)&vtL, g_vt_lo);
    cudaGetSymbolAddress((void**)&pH,  g_p_hi);
    cudaGetSymbolAddress((void**)&pL,  g_p_lo);
    cudaGetSymbolAddress((void**)&cxH, g_ctx_hi);
    cudaGetSymbolAddress((void**)&cxL, g_ctx_lo);
    cudaGetSymbolAddress((void**)&lg,  g_logits);

    // max(tcgen05 need, HMMA need)
    constexpr int SMEM_BIG   = 1024 + 2 * (2 * 128 * 128 + 2 * 128 * 128); // 132096
    constexpr int SMEM_SMALL = 1024 + 2 * (2 * 128 * 128 + 2 * 64 * 128);  //  99328
    cudaFuncSetAttribute(gemm_any<128>,
                         cudaFuncAttributeMaxDynamicSharedMemorySize, SMEM_BIG);
    cudaFuncSetAttribute(gemm_any<64>,
                         cudaFuncAttributeMaxDynamicSharedMemorySize, SMEM_SMALL);

    dim3 wtg(32, 32);
    dim3 wtb(32, 8);
    conv_wT<<<wtg, wtb>>>(wq, wtH + 0u,       wtL + 0u);
    conv_wT<<<wtg, wtb>>>(wk, wtH + 1048576u, wtL + 1048576u);
    conv_wT<<<wtg, wtb>>>(wv, wtH + 2097152u, wtL + 2097152u);
    conv_wT<<<wtg, wtb>>>(wo, wtH + 3145728u, wtL + 3145728u);

    dim3 projGrid(8, 128, 1);

    // Q projection -> head-split
    conv_act<<<16384, 256>>>(q, aH, aL);
    gemm_any<128><<<projGrid, 256, SMEM_BIG>>>(
        aH, aL, 0, wtH + 0u, wtL + 0u, 0, 1024, 1, nullptr, qhH, qhL, bq);
    // K projection
    conv_act<<<16384, 256>>>(k, aH, aL);
    gemm_any<128><<<projGrid, 256, SMEM_BIG>>>(
        aH, aL, 0, wtH + 1048576u, wtL + 1048576u, 0, 1024, 1, nullptr, khH, khL, bk);
    // V projection -> transposed [bsh][d][l]
    conv_act<<<16384, 256>>>(v, aH, aL);
    gemm_any<128><<<projGrid, 256, SMEM_BIG>>>(
        aH, aL, 0, wtH + 2097152u, wtL + 2097152u, 0, 1024, 2, nullptr, vtH, vtL, bv);

    // QK^T logits (scale + mask fused), K=64
    gemm_any<128><<<dim3(8, 8, 256), 256, SMEM_BIG>>>(
        qhH, qhL, 65536, khH, khL, 65536, 64, 3, lg, nullptr, nullptr, mask);

    // softmax -> bf16 hi/lo probs
    softmax_kernel<<<262144, 256>>>();

    // ctx = P @ V  (A = probs [q][k], B = vt [d][l]), K=1024
    gemm_any<64><<<dim3(1, 8, 256), 256, SMEM_SMALL>>>(
        pH, pL, (size_t)1 << 20, vtH, vtL, 65536, 1024, 4, nullptr, cxH, cxL, nullptr);

    // attn_mean
    head_mean_kernel<<<32768, 256>>>(attn_mean);

    // out projection (fp32 + bias)
    gemm_any<128><<<projGrid, 256, SMEM_BIG>>>(
        cxH, cxL, 0, wtH + 3145728u, wtL + 3145728u, 0, 1024, 0, out, nullptr, nullptr, bo);
}